// round 10
// baseline (speedup 1.0000x reference)
#include <cuda_runtime.h>
#include <cuda_bf16.h>
#include <cstdint>

#define M_DIM 64
#define K_DIM 8192
#define N_DIM 8192
#define KBLK  16
#define NTILE 128
#define KSPLIT 4
#define KC    32
#define ITERS ((K_DIM / KSPLIT) / KC)   /* 64 */
#define THREADS 256
#define STAGES 4
#define XSTRIDE 48   /* int8 x rows: 32 data + 16 pad -> conflict-free frags */

// per-stage smem slices (bytes)
#define WC_ST 16384                       /* 128 rows x 8 chunks x 16B codes */
#define X8_ST (64 * XSTRIDE)              /* 3072 */
#define WS_ST (128 * 8)                   /* 1024: [row][2] fp32 */
#define XS_ST (64 * 8)                    /*  512: [row][2] fp32 */
#define OFF_WC 0
#define OFF_X8 (STAGES * WC_ST)                  /* 65536 */
#define OFF_WS (OFF_X8 + STAGES * X8_ST)         /* 77824 */
#define OFF_XS (OFF_WS + STAGES * WS_ST)         /* 81920 */
#define SMEM_TOTAL (OFF_XS + STAGES * XS_ST)     /* 83968 */

#define MAGIC_I 0x4B400000
#define MAGIC_F 12582912.0f

__device__ float  g_scratch[KSPLIT * M_DIM * N_DIM];  // 8 MB fp32 partial slabs
__device__ int8_t g_xi8[M_DIM * K_DIM];               // 512 KB: x as int8 (2x values)

// 2x NVFP4 LUT as integers (sign folded): exact in int8.
__constant__ int c_ilut[16] = { 0, 1, 2, 3, 4, 6, 8, 12,
                                0,-1,-2,-3,-4,-6,-8,-12};

// ---------------------------------------------------------------------------
// Kernel A: x codes -> int8 (2x value). 4 codes per thread via shfl-LUT.
// ---------------------------------------------------------------------------
__global__ void prep_kernel(const int* __restrict__ x) {
    int t    = blockIdx.x * blockDim.x + threadIdx.x;   // < M*K/4
    int lane = threadIdx.x & 31;
    int ilut = c_ilut[lane & 15];
    int4 c = ((const int4*)x)[t];
    int v0 = __shfl_sync(0xffffffffu, ilut, c.x & 15);
    int v1 = __shfl_sync(0xffffffffu, ilut, c.y & 15);
    int v2 = __shfl_sync(0xffffffffu, ilut, c.z & 15);
    int v3 = __shfl_sync(0xffffffffu, ilut, c.w & 15);
    unsigned t01 = __byte_perm((unsigned)v0, (unsigned)v1, 0x0040);
    unsigned t23 = __byte_perm((unsigned)v2, (unsigned)v3, 0x0040);
    ((unsigned*)g_xi8)[t] = __byte_perm(t01, t23, 0x5410);
}

__device__ __forceinline__ unsigned dec4(int c0, int c1, int c2, int c3, int ilut) {
    int v0 = __shfl_sync(0xffffffffu, ilut, c0 & 15);
    int v1 = __shfl_sync(0xffffffffu, ilut, c1 & 15);
    int v2 = __shfl_sync(0xffffffffu, ilut, c2 & 15);
    int v3 = __shfl_sync(0xffffffffu, ilut, c3 & 15);
    unsigned t01 = __byte_perm((unsigned)v0, (unsigned)v1, 0x0040);
    unsigned t23 = __byte_perm((unsigned)v2, (unsigned)v3, 0x0040);
    return __byte_perm(t01, t23, 0x5410);
}

// ---------------------------------------------------------------------------
// Kernel B: exact s8 IMMA GEMM, cp.async 4-stage pipeline, decode-at-use.
// Grid (N/128, KSPLIT=4) = 256 CTAs (single wave at 2 CTA/SM). Per-MMA math
// identical to the round-9 passing kernel (bit-exact per 16-block dequant).
// ---------------------------------------------------------------------------
__global__ void __launch_bounds__(THREADS, 2)
gemm_kernel(const int* __restrict__ w, const float* __restrict__ wsc,
            const float* __restrict__ xsc) {
    extern __shared__ char smem[];

    const int tid  = threadIdx.x;
    const int lane = tid & 31;
    const int warp = tid >> 5;
    const int bn   = blockIdx.x;
    const int k0   = blockIdx.y * (K_DIM / KSPLIT);
    const int ilut = c_ilut[lane & 15];

    const int g  = lane >> 2;
    const int tg = lane & 3;
    const int wr = warp * 16;
    const int rot = (g & 1) << 2;   // chunk-group parity rotation

    // Issue one stage of cp.async (W codes 16KB, X int8 2KB, scales 1.5KB).
    #define ISSUE_STAGE(it)                                                        \
    {                                                                              \
        const int buf_ = (it) & (STAGES - 1);                                      \
        const int kb_  = k0 + (it) * KC;                                           \
        unsigned wdst = (unsigned)__cvta_generic_to_shared(                        \
                            smem + OFF_WC + buf_ * WC_ST);                         \
        _Pragma("unroll")                                                          \
        for (int t = 0; t < 4; ++t) {                                              \
            int p = tid + t * 256;                                                 \
            int row = p >> 3, kq = p & 7;                                          \
            const int* src = w + (long)(bn * NTILE + row) * K_DIM + kb_ + kq * 4;  \
            unsigned d = wdst + (unsigned)((row * 8 +                              \
                              ((kq + ((row & 1) << 2)) & 7)) << 4);                \
            asm volatile("cp.async.cg.shared.global [%0], [%1], 16;\n"             \
                         :: "r"(d), "l"(src) : "memory");                          \
        }                                                                          \
        if (tid < 128) {                                                           \
            int row = tid >> 1, seg = tid & 1;                                     \
            const int8_t* src = g_xi8 + row * K_DIM + kb_ + seg * 16;              \
            unsigned d = (unsigned)__cvta_generic_to_shared(                       \
                smem + OFF_X8 + buf_ * X8_ST + row * XSTRIDE + seg * 16);          \
            asm volatile("cp.async.cg.shared.global [%0], [%1], 16;\n"             \
                         :: "r"(d), "l"(src) : "memory");                          \
        } else {                                                                   \
            int r = tid - 128;                                                     \
            const float* src = wsc + (long)(bn * NTILE + r) * (K_DIM / KBLK)       \
                                   + (kb_ >> 4);                                   \
            unsigned d = (unsigned)__cvta_generic_to_shared(                       \
                smem + OFF_WS + buf_ * WS_ST + r * 8);                             \
            asm volatile("cp.async.ca.shared.global [%0], [%1], 8;\n"              \
                         :: "r"(d), "l"(src) : "memory");                          \
        }                                                                          \
        if (tid < 64) {                                                            \
            const float* src = xsc + tid * (K_DIM / KBLK) + (kb_ >> 4);            \
            unsigned d = (unsigned)__cvta_generic_to_shared(                       \
                smem + OFF_XS + buf_ * XS_ST + tid * 8);                           \
            asm volatile("cp.async.ca.shared.global [%0], [%1], 8;\n"              \
                         :: "r"(d), "l"(src) : "memory");                          \
        }                                                                          \
    }

    // packed accumulators: accp[j][0]=(c0,c1), accp[j][1]=(c2,c3)
    unsigned long long accp[8][2];
    #pragma unroll
    for (int j = 0; j < 8; ++j) { accp[j][0] = 0ull; accp[j][1] = 0ull; }

    unsigned long long magic2;
    asm("mov.b64 %0, {%1, %1};" : "=l"(magic2) : "f"(-MAGIC_F));

    // prologue: STAGES-1 stages in flight
    #pragma unroll
    for (int s = 0; s < STAGES - 1; ++s) {
        ISSUE_STAGE(s);
        asm volatile("cp.async.commit_group;\n" ::: "memory");
    }

    for (int it = 0; it < ITERS; ++it) {
        asm volatile("cp.async.wait_group %0;\n" :: "n"(STAGES - 2) : "memory");
        __syncthreads();
        const int buf = it & (STAGES - 1);

        const char*  WCs = smem + OFF_WC + buf * WC_ST;
        const char*  X8s = smem + OFF_X8 + buf * X8_ST;
        const float* WSs = (const float*)(smem + OFF_WS + buf * WS_ST);
        const float* XSs = (const float*)(smem + OFF_XS + buf * XS_ST);

        // per-chunk hoists: decode A fragments + duplicated W scales
        unsigned a0[2], a1[2];
        unsigned long long wdup[2], w8dup[2];
        #pragma unroll
        for (int b = 0; b < 2; ++b) {
            const int kqr = ((b * 4 + tg) + rot) & 7;
            int4 cA = *(const int4*)(WCs + (((wr + g    ) * 8 + kqr) << 4));
            int4 cB = *(const int4*)(WCs + (((wr + 8 + g) * 8 + kqr) << 4));
            a0[b] = dec4(cA.x, cA.y, cA.z, cA.w, ilut);
            a1[b] = dec4(cB.x, cB.y, cB.z, cB.w, ilut);
            float wsg  = WSs[(wr + g    ) * 2 + b];
            float wsg8 = WSs[(wr + 8 + g) * 2 + b];
            asm("mov.b64 %0, {%1, %1};" : "=l"(wdup[b])
                : "r"(__float_as_uint(wsg)));
            asm("mov.b64 %0, {%1, %1};" : "=l"(w8dup[b])
                : "r"(__float_as_uint(wsg8)));
        }

        #pragma unroll
        for (int j = 0; j < 8; ++j) {
            // packed x-scale pairs for rows (j*8+2tg, j*8+2tg+1), both blocks
            float4 xsq = *(const float4*)(XSs + (j * 8 + 2 * tg) * 2);
            unsigned long long xsp[2];
            asm("mov.b64 %0, {%1, %2};" : "=l"(xsp[0])
                : "r"(__float_as_uint(xsq.x)), "r"(__float_as_uint(xsq.z)));
            asm("mov.b64 %0, {%1, %2};" : "=l"(xsp[1])
                : "r"(__float_as_uint(xsq.y)), "r"(__float_as_uint(xsq.w)));

            #pragma unroll
            for (int b = 0; b < 2; ++b) {
                unsigned bf = *(const unsigned*)(X8s + (j * 8 + g) * XSTRIDE
                                                 + b * 16 + tg * 4);
                int d0, d1, d2, d3;
                asm volatile(
                    "mma.sync.aligned.m16n8k16.row.col.s32.s8.s8.s32 "
                    "{%0,%1,%2,%3}, {%4,%5}, {%6}, {%7,%8,%9,%10};\n"
                    : "=r"(d0), "=r"(d1), "=r"(d2), "=r"(d3)
                    : "r"(a0[b]), "r"(a1[b]), "r"(bf),
                      "r"(0), "r"(0), "r"(0), "r"(0));

                unsigned long long sc01, sc23, p01, p23, f01, f23;
                asm("mul.rn.f32x2 %0, %1, %2;" : "=l"(sc01) : "l"(xsp[b]), "l"(wdup[b]));
                asm("mul.rn.f32x2 %0, %1, %2;" : "=l"(sc23) : "l"(xsp[b]), "l"(w8dup[b]));
                asm("mov.b64 %0, {%1, %2};" : "=l"(p01)
                    : "r"(d0 + MAGIC_I), "r"(d1 + MAGIC_I));
                asm("mov.b64 %0, {%1, %2};" : "=l"(p23)
                    : "r"(d2 + MAGIC_I), "r"(d3 + MAGIC_I));
                asm("add.rn.f32x2 %0, %1, %2;" : "=l"(f01) : "l"(p01), "l"(magic2));
                asm("add.rn.f32x2 %0, %1, %2;" : "=l"(f23) : "l"(p23), "l"(magic2));
                asm("fma.rn.f32x2 %0, %1, %2, %0;" : "+l"(accp[j][0])
                    : "l"(f01), "l"(sc01));
                asm("fma.rn.f32x2 %0, %1, %2, %0;" : "+l"(accp[j][1])
                    : "l"(f23), "l"(sc23));
            }
        }

        // issue the next stage into the buffer freed by compute(it-1)
        if (it + STAGES - 1 < ITERS) ISSUE_STAGE(it + STAGES - 1);
        asm volatile("cp.async.commit_group;\n" ::: "memory");
    }

    // ---- epilogue: plain stores to this split's private slab ----
    float* S = g_scratch + blockIdx.y * (M_DIM * N_DIM);
    const int nbase = bn * NTILE + wr + g;
    #pragma unroll
    for (int j = 0; j < 8; ++j) {
        const int m0 = j * 8 + tg * 2;
        unsigned c0, c1, c2, c3;
        asm("mov.b64 {%0, %1}, %2;" : "=r"(c0), "=r"(c1) : "l"(accp[j][0]));
        asm("mov.b64 {%0, %1}, %2;" : "=r"(c2), "=r"(c3) : "l"(accp[j][1]));
        S[(m0    ) * N_DIM + nbase    ] = __uint_as_float(c0);
        S[(m0 + 1) * N_DIM + nbase    ] = __uint_as_float(c1);
        S[(m0    ) * N_DIM + nbase + 8] = __uint_as_float(c2);
        S[(m0 + 1) * N_DIM + nbase + 8] = __uint_as_float(c3);
    }
    #undef ISSUE_STAGE
}

// ---------------------------------------------------------------------------
// Kernel C: out (fp32 buffer) = fp32(bf16(sum_slabs * gx*gw*0.25 + bias[n]))
// ---------------------------------------------------------------------------
__global__ void finalize_kernel(const float* __restrict__ g1,
                                const float* __restrict__ g2,
                                const float* __restrict__ bias,
                                float* __restrict__ out) {
    int idx = blockIdx.x * blockDim.x + threadIdx.x;
    if (idx >= M_DIM * N_DIM) return;
    const float g = g1[0] * g2[0] * 0.25f;
    const int n = idx & (N_DIM - 1);
    float s = 0.f;
    #pragma unroll
    for (int t = 0; t < KSPLIT; ++t)
        s += g_scratch[idx + t * (M_DIM * N_DIM)];
    float v = fmaf(s, g, bias[n]);
    out[idx] = __bfloat162float(__float2bfloat16(v));
}

// ---------------------------------------------------------------------------
// Inputs identified by element count (all distinct; byte-count fallback).
// ---------------------------------------------------------------------------
extern "C" void kernel_launch(void* const* d_in, const int* in_sizes, int n_in,
                              void* d_out, int out_size) {
    const int*   x    = nullptr;
    const float* xs   = nullptr;
    const int*   wgt  = nullptr;
    const float* wsc  = nullptr;
    const float* bias = nullptr;
    const float* gA   = nullptr;
    const float* gB   = nullptr;

    for (int pass = 0; pass < 2 && !wgt; ++pass) {
        const int mul = (pass == 0) ? 1 : 4;
        x = nullptr; xs = nullptr; wgt = nullptr; wsc = nullptr;
        bias = nullptr; gA = nullptr; gB = nullptr;
        for (int i = 0; i < n_in; ++i) {
            long sz = (long)in_sizes[i];
            if      (sz == (long)M_DIM * K_DIM * mul)          x    = (const int*)  d_in[i];
            else if (sz == (long)M_DIM * (K_DIM/KBLK) * mul)   xs   = (const float*)d_in[i];
            else if (sz == (long)N_DIM * K_DIM * mul)          wgt  = (const int*)  d_in[i];
            else if (sz == (long)N_DIM * (K_DIM/KBLK) * mul)   wsc  = (const float*)d_in[i];
            else if (sz == (long)N_DIM * mul)                  bias = (const float*)d_in[i];
            else if (sz == 1 * mul) { if (!gA) gA = (const float*)d_in[i];
                                      else     gB = (const float*)d_in[i]; }
        }
    }

    cudaFuncSetAttribute(gemm_kernel,
                         cudaFuncAttributeMaxDynamicSharedMemorySize, SMEM_TOTAL);

    prep_kernel<<<(M_DIM * K_DIM / 4) / THREADS, THREADS>>>(x);
    gemm_kernel<<<dim3(N_DIM / NTILE, KSPLIT), THREADS, SMEM_TOTAL>>>(wgt, wsc, xs);
    finalize_kernel<<<(M_DIM * N_DIM) / 256, 256>>>(gA, gB, bias,
                                                    (float*)d_out);
}

// round 11
// speedup vs baseline: 1.0002x; 1.0002x over previous
#include <cuda_runtime.h>
#include <cuda_bf16.h>
#include <cstdint>

#define M_DIM 64
#define K_DIM 8192
#define N_DIM 8192
#define KBLK  16
#define NTILE 128
#define KSPLIT 4
#define KC    32
#define ITERS ((K_DIM / KSPLIT) / KC)   /* 64 */
#define THREADS 256
#define STAGES 4
#define XSTRIDE 48   /* int8 x rows: 32 data + 16 pad -> conflict-free frags */

// per-stage smem slices (bytes)
#define WC_ST 16384                       /* 128 rows x 8 chunks x 16B codes */
#define X8_ST (64 * XSTRIDE)              /* 3072 */
#define WS_ST (128 * 8)                   /* 1024: [row][2] fp32 */
#define XS_ST (64 * 8)                    /*  512: [row][2] fp32 */
#define OFF_WC 0
#define OFF_X8 (STAGES * WC_ST)                  /* 65536 */
#define OFF_WS (OFF_X8 + STAGES * X8_ST)         /* 77824 */
#define OFF_XS (OFF_WS + STAGES * WS_ST)         /* 81920 */
#define SMEM_TOTAL (OFF_XS + STAGES * XS_ST)     /* 83968 */

#define MAGIC_I 0x4B400000
#define MAGIC_F 12582912.0f

__device__ float  g_scratch[KSPLIT * M_DIM * N_DIM];  // 8 MB fp32 partial slabs
__device__ int8_t g_xi8[M_DIM * K_DIM];               // 512 KB: x as int8 (2x values)

// 2x NVFP4 LUT as integers (sign folded): exact in int8.
__constant__ int c_ilut[16] = { 0, 1, 2, 3, 4, 6, 8, 12,
                                0,-1,-2,-3,-4,-6,-8,-12};

// ---------------------------------------------------------------------------
// Kernel A: x codes -> int8 (2x value). 4 codes per thread via shfl-LUT.
// ---------------------------------------------------------------------------
__global__ void prep_kernel(const int* __restrict__ x) {
    int t    = blockIdx.x * blockDim.x + threadIdx.x;   // < M*K/4
    int lane = threadIdx.x & 31;
    int ilut = c_ilut[lane & 15];
    int4 c = ((const int4*)x)[t];
    int v0 = __shfl_sync(0xffffffffu, ilut, c.x & 15);
    int v1 = __shfl_sync(0xffffffffu, ilut, c.y & 15);
    int v2 = __shfl_sync(0xffffffffu, ilut, c.z & 15);
    int v3 = __shfl_sync(0xffffffffu, ilut, c.w & 15);
    unsigned t01 = __byte_perm((unsigned)v0, (unsigned)v1, 0x0040);
    unsigned t23 = __byte_perm((unsigned)v2, (unsigned)v3, 0x0040);
    ((unsigned*)g_xi8)[t] = __byte_perm(t01, t23, 0x5410);
}

__device__ __forceinline__ unsigned dec4(int c0, int c1, int c2, int c3, int ilut) {
    int v0 = __shfl_sync(0xffffffffu, ilut, c0 & 15);
    int v1 = __shfl_sync(0xffffffffu, ilut, c1 & 15);
    int v2 = __shfl_sync(0xffffffffu, ilut, c2 & 15);
    int v3 = __shfl_sync(0xffffffffu, ilut, c3 & 15);
    unsigned t01 = __byte_perm((unsigned)v0, (unsigned)v1, 0x0040);
    unsigned t23 = __byte_perm((unsigned)v2, (unsigned)v3, 0x0040);
    return __byte_perm(t01, t23, 0x5410);
}

// ---------------------------------------------------------------------------
// Kernel B: exact s8 IMMA GEMM, cp.async 4-stage pipeline, decode-at-use.
// Grid (N/128, KSPLIT=4) = 256 CTAs (single wave at 2 CTA/SM). Per-MMA math
// identical to the round-9 passing kernel (bit-exact per 16-block dequant).
// ---------------------------------------------------------------------------
__global__ void __launch_bounds__(THREADS, 2)
gemm_kernel(const int* __restrict__ w, const float* __restrict__ wsc,
            const float* __restrict__ xsc) {
    extern __shared__ char smem[];

    const int tid  = threadIdx.x;
    const int lane = tid & 31;
    const int warp = tid >> 5;
    const int bn   = blockIdx.x;
    const int k0   = blockIdx.y * (K_DIM / KSPLIT);
    const int ilut = c_ilut[lane & 15];

    const int g  = lane >> 2;
    const int tg = lane & 3;
    const int wr = warp * 16;
    const int rot = (g & 1) << 2;   // chunk-group parity rotation

    // Issue one stage of cp.async (W codes 16KB, X int8 2KB, scales 1.5KB).
    #define ISSUE_STAGE(it)                                                        \
    {                                                                              \
        const int buf_ = (it) & (STAGES - 1);                                      \
        const int kb_  = k0 + (it) * KC;                                           \
        unsigned wdst = (unsigned)__cvta_generic_to_shared(                        \
                            smem + OFF_WC + buf_ * WC_ST);                         \
        _Pragma("unroll")                                                          \
        for (int t = 0; t < 4; ++t) {                                              \
            int p = tid + t * 256;                                                 \
            int row = p >> 3, kq = p & 7;                                          \
            const int* src = w + (long)(bn * NTILE + row) * K_DIM + kb_ + kq * 4;  \
            unsigned d = wdst + (unsigned)((row * 8 +                              \
                              ((kq + ((row & 1) << 2)) & 7)) << 4);                \
            asm volatile("cp.async.cg.shared.global [%0], [%1], 16;\n"             \
                         :: "r"(d), "l"(src) : "memory");                          \
        }                                                                          \
        if (tid < 128) {                                                           \
            int row = tid >> 1, seg = tid & 1;                                     \
            const int8_t* src = g_xi8 + row * K_DIM + kb_ + seg * 16;              \
            unsigned d = (unsigned)__cvta_generic_to_shared(                       \
                smem + OFF_X8 + buf_ * X8_ST + row * XSTRIDE + seg * 16);          \
            asm volatile("cp.async.cg.shared.global [%0], [%1], 16;\n"             \
                         :: "r"(d), "l"(src) : "memory");                          \
        } else {                                                                   \
            int r = tid - 128;                                                     \
            const float* src = wsc + (long)(bn * NTILE + r) * (K_DIM / KBLK)       \
                                   + (kb_ >> 4);                                   \
            unsigned d = (unsigned)__cvta_generic_to_shared(                       \
                smem + OFF_WS + buf_ * WS_ST + r * 8);                             \
            asm volatile("cp.async.ca.shared.global [%0], [%1], 8;\n"              \
                         :: "r"(d), "l"(src) : "memory");                          \
        }                                                                          \
        if (tid < 64) {                                                            \
            const float* src = xsc + tid * (K_DIM / KBLK) + (kb_ >> 4);            \
            unsigned d = (unsigned)__cvta_generic_to_shared(                       \
                smem + OFF_XS + buf_ * XS_ST + tid * 8);                           \
            asm volatile("cp.async.ca.shared.global [%0], [%1], 8;\n"              \
                         :: "r"(d), "l"(src) : "memory");                          \
        }                                                                          \
    }

    // packed accumulators: accp[j][0]=(c0,c1), accp[j][1]=(c2,c3)
    unsigned long long accp[8][2];
    #pragma unroll
    for (int j = 0; j < 8; ++j) { accp[j][0] = 0ull; accp[j][1] = 0ull; }

    unsigned long long magic2;
    asm("mov.b64 %0, {%1, %1};" : "=l"(magic2) : "f"(-MAGIC_F));

    // prologue: STAGES-1 stages in flight
    #pragma unroll
    for (int s = 0; s < STAGES - 1; ++s) {
        ISSUE_STAGE(s);
        asm volatile("cp.async.commit_group;\n" ::: "memory");
    }

    for (int it = 0; it < ITERS; ++it) {
        asm volatile("cp.async.wait_group %0;\n" :: "n"(STAGES - 2) : "memory");
        __syncthreads();
        const int buf = it & (STAGES - 1);

        const char*  WCs = smem + OFF_WC + buf * WC_ST;
        const char*  X8s = smem + OFF_X8 + buf * X8_ST;
        const float* WSs = (const float*)(smem + OFF_WS + buf * WS_ST);
        const float* XSs = (const float*)(smem + OFF_XS + buf * XS_ST);

        // per-chunk hoists: decode A fragments + duplicated W scales
        unsigned a0[2], a1[2];
        unsigned long long wdup[2], w8dup[2];
        #pragma unroll
        for (int b = 0; b < 2; ++b) {
            const int kqr = ((b * 4 + tg) + rot) & 7;
            int4 cA = *(const int4*)(WCs + (((wr + g    ) * 8 + kqr) << 4));
            int4 cB = *(const int4*)(WCs + (((wr + 8 + g) * 8 + kqr) << 4));
            a0[b] = dec4(cA.x, cA.y, cA.z, cA.w, ilut);
            a1[b] = dec4(cB.x, cB.y, cB.z, cB.w, ilut);
            float wsg  = WSs[(wr + g    ) * 2 + b];
            float wsg8 = WSs[(wr + 8 + g) * 2 + b];
            asm("mov.b64 %0, {%1, %1};" : "=l"(wdup[b])
                : "r"(__float_as_uint(wsg)));
            asm("mov.b64 %0, {%1, %1};" : "=l"(w8dup[b])
                : "r"(__float_as_uint(wsg8)));
        }

        #pragma unroll
        for (int j = 0; j < 8; ++j) {
            // packed x-scale pairs for rows (j*8+2tg, j*8+2tg+1), both blocks
            float4 xsq = *(const float4*)(XSs + (j * 8 + 2 * tg) * 2);
            unsigned long long xsp[2];
            asm("mov.b64 %0, {%1, %2};" : "=l"(xsp[0])
                : "r"(__float_as_uint(xsq.x)), "r"(__float_as_uint(xsq.z)));
            asm("mov.b64 %0, {%1, %2};" : "=l"(xsp[1])
                : "r"(__float_as_uint(xsq.y)), "r"(__float_as_uint(xsq.w)));

            #pragma unroll
            for (int b = 0; b < 2; ++b) {
                unsigned bf = *(const unsigned*)(X8s + (j * 8 + g) * XSTRIDE
                                                 + b * 16 + tg * 4);
                int d0, d1, d2, d3;
                asm volatile(
                    "mma.sync.aligned.m16n8k16.row.col.s32.s8.s8.s32 "
                    "{%0,%1,%2,%3}, {%4,%5}, {%6}, {%7,%8,%9,%10};\n"
                    : "=r"(d0), "=r"(d1), "=r"(d2), "=r"(d3)
                    : "r"(a0[b]), "r"(a1[b]), "r"(bf),
                      "r"(0), "r"(0), "r"(0), "r"(0));

                unsigned long long sc01, sc23, p01, p23, f01, f23;
                asm("mul.rn.f32x2 %0, %1, %2;" : "=l"(sc01) : "l"(xsp[b]), "l"(wdup[b]));
                asm("mul.rn.f32x2 %0, %1, %2;" : "=l"(sc23) : "l"(xsp[b]), "l"(w8dup[b]));
                asm("mov.b64 %0, {%1, %2};" : "=l"(p01)
                    : "r"(d0 + MAGIC_I), "r"(d1 + MAGIC_I));
                asm("mov.b64 %0, {%1, %2};" : "=l"(p23)
                    : "r"(d2 + MAGIC_I), "r"(d3 + MAGIC_I));
                asm("add.rn.f32x2 %0, %1, %2;" : "=l"(f01) : "l"(p01), "l"(magic2));
                asm("add.rn.f32x2 %0, %1, %2;" : "=l"(f23) : "l"(p23), "l"(magic2));
                asm("fma.rn.f32x2 %0, %1, %2, %0;" : "+l"(accp[j][0])
                    : "l"(f01), "l"(sc01));
                asm("fma.rn.f32x2 %0, %1, %2, %0;" : "+l"(accp[j][1])
                    : "l"(f23), "l"(sc23));
            }
        }

        // issue the next stage into the buffer freed by compute(it-1)
        if (it + STAGES - 1 < ITERS) ISSUE_STAGE(it + STAGES - 1);
        asm volatile("cp.async.commit_group;\n" ::: "memory");
    }

    // ---- epilogue: plain stores to this split's private slab ----
    float* S = g_scratch + blockIdx.y * (M_DIM * N_DIM);
    const int nbase = bn * NTILE + wr + g;
    #pragma unroll
    for (int j = 0; j < 8; ++j) {
        const int m0 = j * 8 + tg * 2;
        unsigned c0, c1, c2, c3;
        asm("mov.b64 {%0, %1}, %2;" : "=r"(c0), "=r"(c1) : "l"(accp[j][0]));
        asm("mov.b64 {%0, %1}, %2;" : "=r"(c2), "=r"(c3) : "l"(accp[j][1]));
        S[(m0    ) * N_DIM + nbase    ] = __uint_as_float(c0);
        S[(m0 + 1) * N_DIM + nbase    ] = __uint_as_float(c1);
        S[(m0    ) * N_DIM + nbase + 8] = __uint_as_float(c2);
        S[(m0 + 1) * N_DIM + nbase + 8] = __uint_as_float(c3);
    }
    #undef ISSUE_STAGE
}

// ---------------------------------------------------------------------------
// Kernel C: out (fp32 buffer) = fp32(bf16(sum_slabs * gx*gw*0.25 + bias[n]))
// ---------------------------------------------------------------------------
__global__ void finalize_kernel(const float* __restrict__ g1,
                                const float* __restrict__ g2,
                                const float* __restrict__ bias,
                                float* __restrict__ out) {
    int idx = blockIdx.x * blockDim.x + threadIdx.x;
    if (idx >= M_DIM * N_DIM) return;
    const float g = g1[0] * g2[0] * 0.25f;
    const int n = idx & (N_DIM - 1);
    float s = 0.f;
    #pragma unroll
    for (int t = 0; t < KSPLIT; ++t)
        s += g_scratch[idx + t * (M_DIM * N_DIM)];
    float v = fmaf(s, g, bias[n]);
    out[idx] = __bfloat162float(__float2bfloat16(v));
}

// ---------------------------------------------------------------------------
// Inputs identified by element count (all distinct; byte-count fallback).
// ---------------------------------------------------------------------------
extern "C" void kernel_launch(void* const* d_in, const int* in_sizes, int n_in,
                              void* d_out, int out_size) {
    const int*   x    = nullptr;
    const float* xs   = nullptr;
    const int*   wgt  = nullptr;
    const float* wsc  = nullptr;
    const float* bias = nullptr;
    const float* gA   = nullptr;
    const float* gB   = nullptr;

    for (int pass = 0; pass < 2 && !wgt; ++pass) {
        const int mul = (pass == 0) ? 1 : 4;
        x = nullptr; xs = nullptr; wgt = nullptr; wsc = nullptr;
        bias = nullptr; gA = nullptr; gB = nullptr;
        for (int i = 0; i < n_in; ++i) {
            long sz = (long)in_sizes[i];
            if      (sz == (long)M_DIM * K_DIM * mul)          x    = (const int*)  d_in[i];
            else if (sz == (long)M_DIM * (K_DIM/KBLK) * mul)   xs   = (const float*)d_in[i];
            else if (sz == (long)N_DIM * K_DIM * mul)          wgt  = (const int*)  d_in[i];
            else if (sz == (long)N_DIM * (K_DIM/KBLK) * mul)   wsc  = (const float*)d_in[i];
            else if (sz == (long)N_DIM * mul)                  bias = (const float*)d_in[i];
            else if (sz == 1 * mul) { if (!gA) gA = (const float*)d_in[i];
                                      else     gB = (const float*)d_in[i]; }
        }
    }

    cudaFuncSetAttribute(gemm_kernel,
                         cudaFuncAttributeMaxDynamicSharedMemorySize, SMEM_TOTAL);

    prep_kernel<<<(M_DIM * K_DIM / 4) / THREADS, THREADS>>>(x);
    gemm_kernel<<<dim3(N_DIM / NTILE, KSPLIT), THREADS, SMEM_TOTAL>>>(wgt, wsc, xs);
    finalize_kernel<<<(M_DIM * N_DIM) / 256, 256>>>(gA, gB, bias,
                                                    (float*)d_out);
}

// round 12
// speedup vs baseline: 1.0019x; 1.0017x over previous
#include <cuda_runtime.h>
#include <cuda_bf16.h>
#include <cstdint>

#define M_DIM 64
#define K_DIM 8192
#define N_DIM 8192
#define KBLK  16
#define NTILE 128
#define KSPLIT 4
#define KC    32
#define ITERS ((K_DIM / KSPLIT) / KC)   /* 64 */
#define THREADS 256
#define STAGES 4
#define XSTRIDE 48   /* int8 x rows: 32 data + 16 pad -> conflict-free frags */

// per-stage smem slices (bytes)
#define WC_ST 16384                       /* 128 rows x 8 chunks x 16B codes */
#define X8_ST (64 * XSTRIDE)              /* 3072 */
#define WS_ST (128 * 8)                   /* 1024: [row][2] fp32 */
#define XS_ST (64 * 8)                    /*  512: [row][2] fp32 */
#define OFF_WC 0
#define OFF_X8 (STAGES * WC_ST)                  /* 65536 */
#define OFF_WS (OFF_X8 + STAGES * X8_ST)         /* 77824 */
#define OFF_XS (OFF_WS + STAGES * WS_ST)         /* 81920 */
#define SMEM_TOTAL (OFF_XS + STAGES * XS_ST)     /* 83968 */

#define MAGIC_I 0x4B400000
#define MAGIC_F 12582912.0f

__device__ float  g_scratch[KSPLIT * M_DIM * N_DIM];  // 8 MB fp32 partial slabs
__device__ int8_t g_xi8[M_DIM * K_DIM];               // 512 KB: x as int8 (2x values)

// 2x NVFP4 LUT as integers (sign folded): exact in int8.
__constant__ int c_ilut[16] = { 0, 1, 2, 3, 4, 6, 8, 12,
                                0,-1,-2,-3,-4,-6,-8,-12};

// ---------------------------------------------------------------------------
// Kernel A: x codes -> int8 (2x value). 4 codes per thread via shfl-LUT.
// ---------------------------------------------------------------------------
__global__ void prep_kernel(const int* __restrict__ x) {
    int t    = blockIdx.x * blockDim.x + threadIdx.x;   // < M*K/4
    int lane = threadIdx.x & 31;
    int ilut = c_ilut[lane & 15];
    int4 c = ((const int4*)x)[t];
    int v0 = __shfl_sync(0xffffffffu, ilut, c.x & 15);
    int v1 = __shfl_sync(0xffffffffu, ilut, c.y & 15);
    int v2 = __shfl_sync(0xffffffffu, ilut, c.z & 15);
    int v3 = __shfl_sync(0xffffffffu, ilut, c.w & 15);
    unsigned t01 = __byte_perm((unsigned)v0, (unsigned)v1, 0x0040);
    unsigned t23 = __byte_perm((unsigned)v2, (unsigned)v3, 0x0040);
    ((unsigned*)g_xi8)[t] = __byte_perm(t01, t23, 0x5410);
}

__device__ __forceinline__ unsigned dec4(int c0, int c1, int c2, int c3, int ilut) {
    int v0 = __shfl_sync(0xffffffffu, ilut, c0 & 15);
    int v1 = __shfl_sync(0xffffffffu, ilut, c1 & 15);
    int v2 = __shfl_sync(0xffffffffu, ilut, c2 & 15);
    int v3 = __shfl_sync(0xffffffffu, ilut, c3 & 15);
    unsigned t01 = __byte_perm((unsigned)v0, (unsigned)v1, 0x0040);
    unsigned t23 = __byte_perm((unsigned)v2, (unsigned)v3, 0x0040);
    return __byte_perm(t01, t23, 0x5410);
}

// ---------------------------------------------------------------------------
// Kernel B: exact s8 IMMA GEMM, cp.async 4-stage pipeline, decode-at-use.
// Grid (N/128, KSPLIT=4) = 256 CTAs (single wave at 2 CTA/SM). Per-MMA math
// identical to the round-9 passing kernel (bit-exact per 16-block dequant).
// ---------------------------------------------------------------------------
__global__ void __launch_bounds__(THREADS, 2)
gemm_kernel(const int* __restrict__ w, const float* __restrict__ wsc,
            const float* __restrict__ xsc) {
    extern __shared__ char smem[];

    const int tid  = threadIdx.x;
    const int lane = tid & 31;
    const int warp = tid >> 5;
    const int bn   = blockIdx.x;
    const int k0   = blockIdx.y * (K_DIM / KSPLIT);
    const int ilut = c_ilut[lane & 15];

    const int g  = lane >> 2;
    const int tg = lane & 3;
    const int wr = warp * 16;
    const int rot = (g & 1) << 2;   // chunk-group parity rotation

    // Issue one stage of cp.async (W codes 16KB, X int8 2KB, scales 1.5KB).
    #define ISSUE_STAGE(it)                                                        \
    {                                                                              \
        const int buf_ = (it) & (STAGES - 1);                                      \
        const int kb_  = k0 + (it) * KC;                                           \
        unsigned wdst = (unsigned)__cvta_generic_to_shared(                        \
                            smem + OFF_WC + buf_ * WC_ST);                         \
        _Pragma("unroll")                                                          \
        for (int t = 0; t < 4; ++t) {                                              \
            int p = tid + t * 256;                                                 \
            int row = p >> 3, kq = p & 7;                                          \
            const int* src = w + (long)(bn * NTILE + row) * K_DIM + kb_ + kq * 4;  \
            unsigned d = wdst + (unsigned)((row * 8 +                              \
                              ((kq + ((row & 1) << 2)) & 7)) << 4);                \
            asm volatile("cp.async.cg.shared.global [%0], [%1], 16;\n"             \
                         :: "r"(d), "l"(src) : "memory");                          \
        }                                                                          \
        if (tid < 128) {                                                           \
            int row = tid >> 1, seg = tid & 1;                                     \
            const int8_t* src = g_xi8 + row * K_DIM + kb_ + seg * 16;              \
            unsigned d = (unsigned)__cvta_generic_to_shared(                       \
                smem + OFF_X8 + buf_ * X8_ST + row * XSTRIDE + seg * 16);          \
            asm volatile("cp.async.cg.shared.global [%0], [%1], 16;\n"             \
                         :: "r"(d), "l"(src) : "memory");                          \
        } else {                                                                   \
            int r = tid - 128;                                                     \
            const float* src = wsc + (long)(bn * NTILE + r) * (K_DIM / KBLK)       \
                                   + (kb_ >> 4);                                   \
            unsigned d = (unsigned)__cvta_generic_to_shared(                       \
                smem + OFF_WS + buf_ * WS_ST + r * 8);                             \
            asm volatile("cp.async.ca.shared.global [%0], [%1], 8;\n"              \
                         :: "r"(d), "l"(src) : "memory");                          \
        }                                                                          \
        if (tid < 64) {                                                            \
            const float* src = xsc + tid * (K_DIM / KBLK) + (kb_ >> 4);            \
            unsigned d = (unsigned)__cvta_generic_to_shared(                       \
                smem + OFF_XS + buf_ * XS_ST + tid * 8);                           \
            asm volatile("cp.async.ca.shared.global [%0], [%1], 8;\n"              \
                         :: "r"(d), "l"(src) : "memory");                          \
        }                                                                          \
    }

    // packed accumulators: accp[j][0]=(c0,c1), accp[j][1]=(c2,c3)
    unsigned long long accp[8][2];
    #pragma unroll
    for (int j = 0; j < 8; ++j) { accp[j][0] = 0ull; accp[j][1] = 0ull; }

    unsigned long long magic2;
    asm("mov.b64 %0, {%1, %1};" : "=l"(magic2) : "f"(-MAGIC_F));

    // prologue: STAGES-1 stages in flight
    #pragma unroll
    for (int s = 0; s < STAGES - 1; ++s) {
        ISSUE_STAGE(s);
        asm volatile("cp.async.commit_group;\n" ::: "memory");
    }

    for (int it = 0; it < ITERS; ++it) {
        asm volatile("cp.async.wait_group %0;\n" :: "n"(STAGES - 2) : "memory");
        __syncthreads();
        const int buf = it & (STAGES - 1);

        const char*  WCs = smem + OFF_WC + buf * WC_ST;
        const char*  X8s = smem + OFF_X8 + buf * X8_ST;
        const float* WSs = (const float*)(smem + OFF_WS + buf * WS_ST);
        const float* XSs = (const float*)(smem + OFF_XS + buf * XS_ST);

        // per-chunk hoists: decode A fragments + duplicated W scales
        unsigned a0[2], a1[2];
        unsigned long long wdup[2], w8dup[2];
        #pragma unroll
        for (int b = 0; b < 2; ++b) {
            const int kqr = ((b * 4 + tg) + rot) & 7;
            int4 cA = *(const int4*)(WCs + (((wr + g    ) * 8 + kqr) << 4));
            int4 cB = *(const int4*)(WCs + (((wr + 8 + g) * 8 + kqr) << 4));
            a0[b] = dec4(cA.x, cA.y, cA.z, cA.w, ilut);
            a1[b] = dec4(cB.x, cB.y, cB.z, cB.w, ilut);
            float wsg  = WSs[(wr + g    ) * 2 + b];
            float wsg8 = WSs[(wr + 8 + g) * 2 + b];
            asm("mov.b64 %0, {%1, %1};" : "=l"(wdup[b])
                : "r"(__float_as_uint(wsg)));
            asm("mov.b64 %0, {%1, %1};" : "=l"(w8dup[b])
                : "r"(__float_as_uint(wsg8)));
        }

        #pragma unroll
        for (int j = 0; j < 8; ++j) {
            // packed x-scale pairs for rows (j*8+2tg, j*8+2tg+1), both blocks
            float4 xsq = *(const float4*)(XSs + (j * 8 + 2 * tg) * 2);
            unsigned long long xsp[2];
            asm("mov.b64 %0, {%1, %2};" : "=l"(xsp[0])
                : "r"(__float_as_uint(xsq.x)), "r"(__float_as_uint(xsq.z)));
            asm("mov.b64 %0, {%1, %2};" : "=l"(xsp[1])
                : "r"(__float_as_uint(xsq.y)), "r"(__float_as_uint(xsq.w)));

            #pragma unroll
            for (int b = 0; b < 2; ++b) {
                unsigned bf = *(const unsigned*)(X8s + (j * 8 + g) * XSTRIDE
                                                 + b * 16 + tg * 4);
                int d0, d1, d2, d3;
                asm volatile(
                    "mma.sync.aligned.m16n8k16.row.col.s32.s8.s8.s32 "
                    "{%0,%1,%2,%3}, {%4,%5}, {%6}, {%7,%8,%9,%10};\n"
                    : "=r"(d0), "=r"(d1), "=r"(d2), "=r"(d3)
                    : "r"(a0[b]), "r"(a1[b]), "r"(bf),
                      "r"(0), "r"(0), "r"(0), "r"(0));

                unsigned long long sc01, sc23, p01, p23, f01, f23;
                asm("mul.rn.f32x2 %0, %1, %2;" : "=l"(sc01) : "l"(xsp[b]), "l"(wdup[b]));
                asm("mul.rn.f32x2 %0, %1, %2;" : "=l"(sc23) : "l"(xsp[b]), "l"(w8dup[b]));
                asm("mov.b64 %0, {%1, %2};" : "=l"(p01)
                    : "r"(d0 + MAGIC_I), "r"(d1 + MAGIC_I));
                asm("mov.b64 %0, {%1, %2};" : "=l"(p23)
                    : "r"(d2 + MAGIC_I), "r"(d3 + MAGIC_I));
                asm("add.rn.f32x2 %0, %1, %2;" : "=l"(f01) : "l"(p01), "l"(magic2));
                asm("add.rn.f32x2 %0, %1, %2;" : "=l"(f23) : "l"(p23), "l"(magic2));
                asm("fma.rn.f32x2 %0, %1, %2, %0;" : "+l"(accp[j][0])
                    : "l"(f01), "l"(sc01));
                asm("fma.rn.f32x2 %0, %1, %2, %0;" : "+l"(accp[j][1])
                    : "l"(f23), "l"(sc23));
            }
        }

        // issue the next stage into the buffer freed by compute(it-1)
        if (it + STAGES - 1 < ITERS) ISSUE_STAGE(it + STAGES - 1);
        asm volatile("cp.async.commit_group;\n" ::: "memory");
    }

    // ---- epilogue: plain stores to this split's private slab ----
    float* S = g_scratch + blockIdx.y * (M_DIM * N_DIM);
    const int nbase = bn * NTILE + wr + g;
    #pragma unroll
    for (int j = 0; j < 8; ++j) {
        const int m0 = j * 8 + tg * 2;
        unsigned c0, c1, c2, c3;
        asm("mov.b64 {%0, %1}, %2;" : "=r"(c0), "=r"(c1) : "l"(accp[j][0]));
        asm("mov.b64 {%0, %1}, %2;" : "=r"(c2), "=r"(c3) : "l"(accp[j][1]));
        S[(m0    ) * N_DIM + nbase    ] = __uint_as_float(c0);
        S[(m0 + 1) * N_DIM + nbase    ] = __uint_as_float(c1);
        S[(m0    ) * N_DIM + nbase + 8] = __uint_as_float(c2);
        S[(m0 + 1) * N_DIM + nbase + 8] = __uint_as_float(c3);
    }
    #undef ISSUE_STAGE
}

// ---------------------------------------------------------------------------
// Kernel C: out (fp32 buffer) = fp32(bf16(sum_slabs * gx*gw*0.25 + bias[n]))
// ---------------------------------------------------------------------------
__global__ void finalize_kernel(const float* __restrict__ g1,
                                const float* __restrict__ g2,
                                const float* __restrict__ bias,
                                float* __restrict__ out) {
    int idx = blockIdx.x * blockDim.x + threadIdx.x;
    if (idx >= M_DIM * N_DIM) return;
    const float g = g1[0] * g2[0] * 0.25f;
    const int n = idx & (N_DIM - 1);
    float s = 0.f;
    #pragma unroll
    for (int t = 0; t < KSPLIT; ++t)
        s += g_scratch[idx + t * (M_DIM * N_DIM)];
    float v = fmaf(s, g, bias[n]);
    out[idx] = __bfloat162float(__float2bfloat16(v));
}

// ---------------------------------------------------------------------------
// Inputs identified by element count (all distinct; byte-count fallback).
// ---------------------------------------------------------------------------
extern "C" void kernel_launch(void* const* d_in, const int* in_sizes, int n_in,
                              void* d_out, int out_size) {
    const int*   x    = nullptr;
    const float* xs   = nullptr;
    const int*   wgt  = nullptr;
    const float* wsc  = nullptr;
    const float* bias = nullptr;
    const float* gA   = nullptr;
    const float* gB   = nullptr;

    for (int pass = 0; pass < 2 && !wgt; ++pass) {
        const int mul = (pass == 0) ? 1 : 4;
        x = nullptr; xs = nullptr; wgt = nullptr; wsc = nullptr;
        bias = nullptr; gA = nullptr; gB = nullptr;
        for (int i = 0; i < n_in; ++i) {
            long sz = (long)in_sizes[i];
            if      (sz == (long)M_DIM * K_DIM * mul)          x    = (const int*)  d_in[i];
            else if (sz == (long)M_DIM * (K_DIM/KBLK) * mul)   xs   = (const float*)d_in[i];
            else if (sz == (long)N_DIM * K_DIM * mul)          wgt  = (const int*)  d_in[i];
            else if (sz == (long)N_DIM * (K_DIM/KBLK) * mul)   wsc  = (const float*)d_in[i];
            else if (sz == (long)N_DIM * mul)                  bias = (const float*)d_in[i];
            else if (sz == 1 * mul) { if (!gA) gA = (const float*)d_in[i];
                                      else     gB = (const float*)d_in[i]; }
        }
    }

    cudaFuncSetAttribute(gemm_kernel,
                         cudaFuncAttributeMaxDynamicSharedMemorySize, SMEM_TOTAL);

    prep_kernel<<<(M_DIM * K_DIM / 4) / THREADS, THREADS>>>(x);
    gemm_kernel<<<dim3(N_DIM / NTILE, KSPLIT), THREADS, SMEM_TOTAL>>>(wgt, wsc, xs);
    finalize_kernel<<<(M_DIM * N_DIM) / 256, 256>>>(gA, gB, bias,
                                                    (float*)d_out);
}